// round 6
// baseline (speedup 1.0000x reference)
#include <cuda_runtime.h>

// SphericalExpansion: per-edge radial×angular outer product scattered into
// out[idx_i, z[idx_j], n, m]  (20000, 4, 8, 16) fp32.
//
// Two edges per warp (halves). Compute role: lane p=(h, l=pos>>2, nl=pos&3)
// evaluates rows (l,nl) and (l,nl+4) of edge e0+h via ONE packed-f32x2
// polynomial in B (Estrin scheme, depth 4):
//   g_k = exp(-2(d-c_k)^2) = A * B^k * C_k,  A=exp(-2d^2), B=exp(4d/3)
//   acc[row] = A*fc * P(B),  P coeffs = W[row,k]*C_k
// Bridge: row placement makes each reader's 4 fetches come from a uniform
// register -> 4 shuffles, 0 selects. Scatter: lane (h,q) commits quads q and
// q+16 via red.global.add.v4.f32. idx chain prefetched one iter ahead.

#define PI_F 3.14159265358979f

typedef unsigned long long u64_t;

__device__ __forceinline__ u64_t pack2(float lo, float hi) {
    u64_t r; asm("mov.b64 %0, {%1, %2};" : "=l"(r) : "f"(lo), "f"(hi)); return r;
}
__device__ __forceinline__ void unpack2(u64_t v, float& lo, float& hi) {
    asm("mov.b64 {%0, %1}, %2;" : "=f"(lo), "=f"(hi) : "l"(v));
}
__device__ __forceinline__ u64_t fma2(u64_t a, u64_t b, u64_t c) {
    u64_t d; asm("fma.rn.f32x2 %0, %1, %2, %3;" : "=l"(d) : "l"(a), "l"(b), "l"(c));
    return d;
}
__device__ __forceinline__ u64_t mul2(u64_t a, u64_t b) {
    u64_t d; asm("mul.rn.f32x2 %0, %1, %2;" : "=l"(d) : "l"(a), "l"(b));
    return d;
}
__device__ __forceinline__ void red_add_v4(float* p, float a, float b, float c, float d) {
    asm volatile("red.global.add.v4.f32 [%0], {%1,%2,%3,%4};"
                 :: "l"(p), "f"(a), "f"(b), "f"(c), "f"(d) : "memory");
}

__global__ __launch_bounds__(256)
void sph_expand_kernel(
    const float* __restrict__ dist,
    const float* __restrict__ dirs,
    const float* __restrict__ W,      // (4, 8, 16) row-major = (32, 16)
    const int*   __restrict__ zarr,   // (N_ATOMS)
    const int*   __restrict__ idx_i,
    const int*   __restrict__ idx_j,
    float*       __restrict__ out,    // (N_ATOMS, 4, 8, 16)
    int n_edges)
{
    const unsigned FULL = 0xffffffffu;
    const int lane = threadIdx.x & 31;
    const int h    = lane >> 4;        // which edge of the pair
    const int pos  = lane & 15;

    const int gw = (blockIdx.x * blockDim.x + threadIdx.x) >> 5;
    const int nw = (gridDim.x * blockDim.x) >> 5;

    // ---- compute role: rows (l, nl) and (l, nl+4), l = pos>>2, nl = pos&3 ----
    const int lrow = pos >> 2;
    const int nl   = pos & 3;
    const int ln0  = lrow * 8 + nl;
    const int ln1  = ln0 + 4;

    // Packed W rows, pre-scaled by C_k = exp(-2 c_k^2).
    u64_t wp[16];
    #pragma unroll
    for (int k = 0; k < 16; ++k) {
        float ck = (float)k * (5.0f / 15.0f);
        float C  = __expf(-2.0f * ck * ck);
        wp[k] = pack2(W[ln0 * 16 + k] * C, W[ln1 * 16 + k] * C);
    }

    // ---- scatter role: lane (h,q) with q=pos -> quads q and q+16 ----
    const int n0 = pos >> 2;
    const int mq = pos & 3;
    const int lA = (mq == 0) ? 0 : (mq == 3 ? 3 : 2);
    const int lB = (mq == 0) ? 1 : (mq == 1 ? 2 : 3);
    const int srcA = (lane & 16) + lA * 4 + n0;
    const int srcB = (lane & 16) + lB * 4 + n0;

    int e0 = 2 * gw;
    if (e0 >= n_edges) return;

    // Prologue: this iteration's index chain.
    int le0 = e0 + h; if (le0 > n_edges - 1) le0 = n_edges - 1;
    int ii  = idx_i[le0];
    int zj  = zarr[idx_j[le0]];

    while (true) {
        // ---- prefetch NEXT iteration's index chain only ----
        const int e0n = e0 + 2 * nw;
        int iiN = 0, zjN = 0;
        if (e0n < n_edges) {
            int leN = e0n + h; if (leN > n_edges - 1) leN = n_edges - 1;
            iiN = idx_i[leN];
            zjN = zarr[idx_j[leN]];
        }

        const int  myE   = e0 + h;
        const bool valid = myE < n_edges;
        const int  le    = valid ? myE : (n_edges - 1);

        const float d  = dist[le];
        const float x  = dirs[3 * le + 0];
        const float y  = dirs[3 * le + 1];
        const float zc = dirs[3 * le + 2];

        // cutoff + radial factorization scalars (lane-local, edge h)
        float t  = fminf(fmaxf((d - 4.5f) * 2.0f, 0.0f), 1.0f);
        float fc = 0.5f * (__cosf(t * PI_F) + 1.0f);
        float A  = __expf(-2.0f * d * d);
        float B  = __expf((4.0f / 3.0f) * d);
        float sc = A * fc;

        // ---- packed Estrin polynomial (depth 4) ----
        const u64_t Bp = pack2(B, B);
        const u64_t B2 = mul2(Bp, Bp);
        const u64_t B4 = mul2(B2, B2);
        const u64_t B8 = mul2(B4, B4);

        u64_t p0 = fma2(wp[1],  Bp, wp[0]);
        u64_t p1 = fma2(wp[3],  Bp, wp[2]);
        u64_t p2 = fma2(wp[5],  Bp, wp[4]);
        u64_t p3 = fma2(wp[7],  Bp, wp[6]);
        u64_t p4 = fma2(wp[9],  Bp, wp[8]);
        u64_t p5 = fma2(wp[11], Bp, wp[10]);
        u64_t p6 = fma2(wp[13], Bp, wp[12]);
        u64_t p7 = fma2(wp[15], Bp, wp[14]);

        u64_t q0 = fma2(p1, B2, p0);
        u64_t q1 = fma2(p3, B2, p2);
        u64_t q2 = fma2(p5, B2, p4);
        u64_t q3 = fma2(p7, B2, p6);

        u64_t r0 = fma2(q1, B4, q0);
        u64_t r1 = fma2(q3, B4, q2);

        u64_t acc = fma2(r1, B8, r0);
        acc = mul2(acc, pack2(sc, sc));

        float c0, c1;                 // c0: row (l,nl)   c1: row (l,nl+4)
        unpack2(acc, c0, c1);

        // ---- bridge: 4 shuffles, uniform source registers ----
        const float aA0 = __shfl_sync(FULL, c0, srcA);
        const float aB0 = __shfl_sync(FULL, c0, srcB);
        const float aA1 = __shfl_sync(FULL, c1, srcA);
        const float aB1 = __shfl_sync(FULL, c1, srcB);

        // ---- real spherical harmonics l<=3 (this half's direction) ----
        const float x2 = x * x, y2 = y * y, z2 = zc * zc;
        const float Y0  = 0.28209479177387814f;
        const float Y1  = 0.4886025119029199f * y;
        const float Y2  = 0.4886025119029199f * zc;
        const float Y3  = 0.4886025119029199f * x;
        const float Y4  = 1.0925484305920792f * x * y;
        const float Y5  = 1.0925484305920792f * y * zc;
        const float Y6  = 0.31539156525252005f * (3.0f * z2 - 1.0f);
        const float Y7  = 1.0925484305920792f * x * zc;
        const float Y8  = 0.5462742152960396f * (x2 - y2);
        const float Y9  = 0.5900435899266435f * y * (3.0f * x2 - y2);
        const float Y10 = 2.890611442640554f  * x * y * zc;
        const float Y11 = 0.4570457994644658f * y * (5.0f * z2 - 1.0f);
        const float Y12 = 0.3731763325901154f * zc * (5.0f * z2 - 3.0f);
        const float Y13 = 0.4570457994644658f * x * (5.0f * z2 - 1.0f);
        const float Y14 = 1.445305721320277f  * zc * (x2 - y2);
        const float Y15 = 0.5900435899266435f * x * (x2 - 3.0f * y2);

        float s0, s1, s2, s3;
        if (mq == 0)      { s0 = Y0;  s1 = Y1;  s2 = Y2;  s3 = Y3;  }
        else if (mq == 1) { s0 = Y4;  s1 = Y5;  s2 = Y6;  s3 = Y7;  }
        else if (mq == 2) { s0 = Y8;  s1 = Y9;  s2 = Y10; s3 = Y11; }
        else              { s0 = Y12; s1 = Y13; s2 = Y14; s3 = Y15; }

        // out offset: ((ii*4 + zj)*8 + n)*16 + mq*4 ; quads q and q+16.
        const size_t base = ((size_t)ii * 4 + (size_t)zj) * 128 + (size_t)pos * 4;
        if (valid) {
            red_add_v4(out + base,      aA0 * s0, aB0 * s1, aB0 * s2, aB0 * s3);
            red_add_v4(out + base + 64, aA1 * s0, aB1 * s1, aB1 * s2, aB1 * s3);
        }

        if (e0n >= n_edges) break;
        e0 = e0n;
        ii = iiN;
        zj = zjN;
    }
}

extern "C" void kernel_launch(void* const* d_in, const int* in_sizes, int n_in,
                              void* d_out, int out_size) {
    const float* dist = (const float*)d_in[0];
    const float* dirs = (const float*)d_in[1];
    const float* W    = (const float*)d_in[2];
    // d_in[3] = centers: analytic linspace(0, RC, 16)
    const int* z      = (const int*)d_in[4];
    const int* idx_i  = (const int*)d_in[5];
    const int* idx_j  = (const int*)d_in[6];
    const int n_edges = in_sizes[0];

    cudaMemsetAsync(d_out, 0, (size_t)out_size * sizeof(float), 0);

    const int block = 256;
    const int grid  = 2368;    // 148 SMs x 16 blocks, grid-stride over edge pairs
    sph_expand_kernel<<<grid, block>>>(dist, dirs, W, z, idx_i, idx_j,
                                       (float*)d_out, n_edges);
}

// round 7
// speedup vs baseline: 1.1320x; 1.1320x over previous
#include <cuda_runtime.h>

// SphericalExpansion: per-edge radial×angular outer product scattered into
// out[idx_i, z[idx_j], n, m]  (20000, 4, 8, 16) fp32.
//
// Phase 1 (build_rid): rbase[e] = (idx_i[e]*4 + zarr[idx_j[e]]) * 128
//   -- removes the 2-deep dependent index chain from the hot loop.
// Phase 2: two edges per warp (halves). Compute role: lane p=(h, l=pos>>2,
// nl=pos&3) evaluates rows (l,nl),(l,nl+4) of edge e0+h via ONE packed-f32x2
// Horner:
//   g_k = exp(-2(d-c_k)^2) = A * B^k * C_k,  A=exp(-2d^2), B=exp(4d/3)
//   acc[row] = A*fc * Horner_k( W[row,k]*C_k ; B )      (B lane-local)
// Bridge: row placement makes each reader's 4 fetches come from a uniform
// register -> 4 shuffles, 0 selects. Scatter: lane (h,q) commits quads q and
// q+16 via red.global.add.v4.f32.

#define PI_F 3.14159265358979f
#define MAX_EDGES 800000

__device__ int g_rbase[MAX_EDGES];

typedef unsigned long long u64_t;

__device__ __forceinline__ u64_t pack2(float lo, float hi) {
    u64_t r; asm("mov.b64 %0, {%1, %2};" : "=l"(r) : "f"(lo), "f"(hi)); return r;
}
__device__ __forceinline__ void unpack2(u64_t v, float& lo, float& hi) {
    asm("mov.b64 {%0, %1}, %2;" : "=f"(lo), "=f"(hi) : "l"(v));
}
__device__ __forceinline__ u64_t fma2(u64_t a, u64_t b, u64_t c) {
    u64_t d; asm("fma.rn.f32x2 %0, %1, %2, %3;" : "=l"(d) : "l"(a), "l"(b), "l"(c));
    return d;
}
__device__ __forceinline__ u64_t mul2(u64_t a, u64_t b) {
    u64_t d; asm("mul.rn.f32x2 %0, %1, %2;" : "=l"(d) : "l"(a), "l"(b));
    return d;
}
__device__ __forceinline__ void red_add_v4(float* p, float a, float b, float c, float d) {
    asm volatile("red.global.add.v4.f32 [%0], {%1,%2,%3,%4};"
                 :: "l"(p), "f"(a), "f"(b), "f"(c), "f"(d) : "memory");
}

__global__ __launch_bounds__(512)
void build_rid_kernel(const int* __restrict__ idx_i,
                      const int* __restrict__ idx_j,
                      const int* __restrict__ zarr,
                      int n_edges)
{
    int e = blockIdx.x * blockDim.x + threadIdx.x;
    if (e < n_edges)
        g_rbase[e] = (idx_i[e] * 4 + zarr[idx_j[e]]) * 128;
}

__global__ __launch_bounds__(256)
void sph_expand_kernel(
    const float* __restrict__ dist,
    const float* __restrict__ dirs,
    const float* __restrict__ W,      // (4, 8, 16) row-major = (32, 16)
    float*       __restrict__ out,    // (N_ATOMS, 4, 8, 16)
    int n_edges)
{
    const unsigned FULL = 0xffffffffu;
    const int lane = threadIdx.x & 31;
    const int h    = lane >> 4;        // which edge of the pair
    const int pos  = lane & 15;

    const int gw = (blockIdx.x * blockDim.x + threadIdx.x) >> 5;
    const int nw = (gridDim.x * blockDim.x) >> 5;

    // ---- compute role: rows (l, nl) and (l, nl+4), l = pos>>2, nl = pos&3 ----
    const int lrow = pos >> 2;
    const int nl   = pos & 3;
    const int ln0  = lrow * 8 + nl;
    const int ln1  = ln0 + 4;

    // Packed W rows, pre-scaled by C_k = exp(-2 c_k^2).
    u64_t wp[16];
    #pragma unroll
    for (int k = 0; k < 16; ++k) {
        float ck = (float)k * (5.0f / 15.0f);
        float C  = __expf(-2.0f * ck * ck);
        wp[k] = pack2(W[ln0 * 16 + k] * C, W[ln1 * 16 + k] * C);
    }

    // ---- scatter role: lane (h,q) with q=pos -> quads q and q+16 ----
    const int n0 = pos >> 2;
    const int mq = pos & 3;
    const int lA = (mq == 0) ? 0 : (mq == 3 ? 3 : 2);
    const int lB = (mq == 0) ? 1 : (mq == 1 ? 2 : 3);
    const int srcA = (lane & 16) + lA * 4 + n0;
    const int srcB = (lane & 16) + lB * 4 + n0;

    for (int e0 = 2 * gw; e0 < n_edges; e0 += 2 * nw) {
        const int  myE   = e0 + h;
        const bool valid = myE < n_edges;
        const int  le    = valid ? myE : (n_edges - 1);

        const int   rb = g_rbase[le];       // independent single load
        const float d  = dist[le];
        const float x  = dirs[3 * le + 0];
        const float y  = dirs[3 * le + 1];
        const float zc = dirs[3 * le + 2];

        // cutoff + radial factorization scalars (lane-local, edge h)
        float t  = fminf(fmaxf((d - 4.5f) * 2.0f, 0.0f), 1.0f);
        float fc = 0.5f * (__cosf(t * PI_F) + 1.0f);
        float A  = __expf(-2.0f * d * d);
        float B  = __expf((4.0f / 3.0f) * d);
        float sc = A * fc;

        // ---- packed Horner: both rows at once ----
        const u64_t Bp  = pack2(B, B);
        u64_t acc = wp[15];
        #pragma unroll
        for (int k = 14; k >= 0; --k) acc = fma2(acc, Bp, wp[k]);
        acc = mul2(acc, pack2(sc, sc));

        float c0, c1;                 // c0: row (l,nl)   c1: row (l,nl+4)
        unpack2(acc, c0, c1);

        // ---- bridge: 4 shuffles, uniform source registers ----
        const float aA0 = __shfl_sync(FULL, c0, srcA);
        const float aB0 = __shfl_sync(FULL, c0, srcB);
        const float aA1 = __shfl_sync(FULL, c1, srcA);
        const float aB1 = __shfl_sync(FULL, c1, srcB);

        // ---- real spherical harmonics l<=3 (this half's direction) ----
        const float x2 = x * x, y2 = y * y, z2 = zc * zc;
        const float Y0  = 0.28209479177387814f;
        const float Y1  = 0.4886025119029199f * y;
        const float Y2  = 0.4886025119029199f * zc;
        const float Y3  = 0.4886025119029199f * x;
        const float Y4  = 1.0925484305920792f * x * y;
        const float Y5  = 1.0925484305920792f * y * zc;
        const float Y6  = 0.31539156525252005f * (3.0f * z2 - 1.0f);
        const float Y7  = 1.0925484305920792f * x * zc;
        const float Y8  = 0.5462742152960396f * (x2 - y2);
        const float Y9  = 0.5900435899266435f * y * (3.0f * x2 - y2);
        const float Y10 = 2.890611442640554f  * x * y * zc;
        const float Y11 = 0.4570457994644658f * y * (5.0f * z2 - 1.0f);
        const float Y12 = 0.3731763325901154f * zc * (5.0f * z2 - 3.0f);
        const float Y13 = 0.4570457994644658f * x * (5.0f * z2 - 1.0f);
        const float Y14 = 1.445305721320277f  * zc * (x2 - y2);
        const float Y15 = 0.5900435899266435f * x * (x2 - 3.0f * y2);

        float s0, s1, s2, s3;
        if (mq == 0)      { s0 = Y0;  s1 = Y1;  s2 = Y2;  s3 = Y3;  }
        else if (mq == 1) { s0 = Y4;  s1 = Y5;  s2 = Y6;  s3 = Y7;  }
        else if (mq == 2) { s0 = Y8;  s1 = Y9;  s2 = Y10; s3 = Y11; }
        else              { s0 = Y12; s1 = Y13; s2 = Y14; s3 = Y15; }

        // out offset: rbase + quad*4 ; quads q and q+16.
        const size_t base = (size_t)rb + (size_t)pos * 4;
        if (valid) {
            red_add_v4(out + base,      aA0 * s0, aB0 * s1, aB0 * s2, aB0 * s3);
            red_add_v4(out + base + 64, aA1 * s0, aB1 * s1, aB1 * s2, aB1 * s3);
        }
    }
}

extern "C" void kernel_launch(void* const* d_in, const int* in_sizes, int n_in,
                              void* d_out, int out_size) {
    const float* dist = (const float*)d_in[0];
    const float* dirs = (const float*)d_in[1];
    const float* W    = (const float*)d_in[2];
    // d_in[3] = centers: analytic linspace(0, RC, 16)
    const int* z      = (const int*)d_in[4];
    const int* idx_i  = (const int*)d_in[5];
    const int* idx_j  = (const int*)d_in[6];
    int n_edges = in_sizes[0];
    if (n_edges > MAX_EDGES) n_edges = MAX_EDGES;   // scratch capacity (spec: 800000)

    cudaMemsetAsync(d_out, 0, (size_t)out_size * sizeof(float), 0);

    build_rid_kernel<<<(n_edges + 511) / 512, 512>>>(idx_i, idx_j, z, n_edges);

    const int block = 256;
    const int grid  = 2368;    // 148 SMs x 16 blocks, grid-stride over edge pairs
    sph_expand_kernel<<<grid, block>>>(dist, dirs, W, (float*)d_out, n_edges);
}